// round 7
// baseline (speedup 1.0000x reference)
#include <cuda_runtime.h>
#include <cuda_fp16.h>
#include <cstdint>

#define NUM_EDGE  14
#define NUM_NODES 10000
#define BATCH     8192
#define EDGE_IN   1536
#define HET_IN    1792
#define DOUT      128

__device__ __half g_agg[(size_t)BATCH * HET_IN];
__device__ __half g_WE [(size_t)NUM_EDGE * EDGE_IN * DOUT];
__device__ __half g_WH [(size_t)HET_IN * DOUT];

__device__ __forceinline__ uint32_t f2h2(float x, float y) {
    __half2 h = __floats2half2_rn(x, y);
    return *(uint32_t*)&h;
}

__device__ __forceinline__ void cp16(uint32_t s, const void* g) {
    asm volatile("cp.async.cg.shared.global [%0], [%1], 16;\n" :: "r"(s), "l"(g));
}
__device__ __forceinline__ void cp_commit() { asm volatile("cp.async.commit_group;\n"); }
template <int N> __device__ __forceinline__ void cp_wait() {
    asm volatile("cp.async.wait_group %0;\n" :: "n"(N));
}

__device__ __forceinline__ void ldsm_x4(uint32_t* r, uint32_t a) {
    asm volatile("ldmatrix.sync.aligned.m8n8.x4.shared.b16 {%0,%1,%2,%3}, [%4];"
        : "=r"(r[0]), "=r"(r[1]), "=r"(r[2]), "=r"(r[3]) : "r"(a));
}
__device__ __forceinline__ void ldsm_x4_t(uint32_t* r, uint32_t a) {
    asm volatile("ldmatrix.sync.aligned.m8n8.x4.trans.shared.b16 {%0,%1,%2,%3}, [%4];"
        : "=r"(r[0]), "=r"(r[1]), "=r"(r[2]), "=r"(r[3]) : "r"(a));
}
__device__ __forceinline__ void sts128(uint32_t a, uint32_t x, uint32_t y, uint32_t z, uint32_t w) {
    asm volatile("st.shared.v4.b32 [%0], {%1,%2,%3,%4};" :: "r"(a), "r"(x), "r"(y), "r"(z), "r"(w));
}

__device__ __forceinline__ void mma_f16(float* c, const uint32_t* a, const uint32_t* b) {
    asm volatile(
        "mma.sync.aligned.m16n8k16.row.col.f32.f16.f16.f32 "
        "{%0,%1,%2,%3}, {%4,%5,%6,%7}, {%8,%9}, {%0,%1,%2,%3};\n"
        : "+f"(c[0]), "+f"(c[1]), "+f"(c[2]), "+f"(c[3])
        : "r"(a[0]), "r"(a[1]), "r"(a[2]), "r"(a[3]), "r"(b[0]), "r"(b[1]));
}

__global__ void cvt_to_half(const float4* __restrict__ s, __half2* __restrict__ d, int n4) {
    int i = blockIdx.x * blockDim.x + threadIdx.x;
    if (i < n4) {
        float4 v = s[i];
        d[2 * i]     = __floats2half2_rn(v.x, v.y);
        d[2 * i + 1] = __floats2half2_rn(v.z, v.w);
    }
}

// ============================================================================
// GEMM1 (EDGE): 512 threads, BM=128, 16 warps (warp tile 32x32), 4-slot ring,
// two K-tiles per barrier. A gathered fp32 -> fp16 at STS. Out -> g_agg fp16.
// ============================================================================
__global__ void __launch_bounds__(512, 2) hetagg_edge(
    const float* __restrict__ Afeat,
    const int*   __restrict__ gid,
    const float* __restrict__ ball)
{
    constexpr int KT    = EDGE_IN / 32;     // 48
    constexpr int NI    = KT / 2;           // 24
    constexpr int A_ST  = 128 * 80;         // 10240
    constexpr int B_ST  = 32 * 256;         // 8192
    constexpr int OFF_B = 4 * A_ST;

    extern __shared__ char smem[];
    const uint32_t sb = (uint32_t)__cvta_generic_to_shared(smem);

    const int e    = blockIdx.y;
    const int tid  = threadIdx.x;
    const int l    = tid & 31;
    const int warp = tid >> 5;
    const int wm   = warp >> 2;     // 0..3 (32-row band)
    const int wn   = warp & 3;      // 0..3 (32-col band)
    const int m0   = blockIdx.x * 128;

    // ---- B loader: 1 cp16/thread/ktile. row tid>>4 (0..31), chunk tid&15.
    const __half* Bh = g_WE + (size_t)e * EDGE_IN * DOUT;
    const int bk = tid >> 4;
    const int bc = tid & 15;
    const __half* bsrc = Bh + (size_t)bk * DOUT + bc * 8;
    const uint32_t bdst = sb + OFF_B + bk * 256 + ((bc >> 3) * 128) + (((bc & 7) ^ (bk & 7)) * 16);
    auto cpB = [&](int s, int kt) {
        cp16(bdst + s * B_ST, bsrc + (size_t)kt * 32 * DOUT);
    };

    // ---- A loader: 4 threads/row, 8 floats (2 float4) each per ktile.
    const int arow = tid >> 2, aq = tid & 3;
    const float* agF = Afeat + (size_t)e * NUM_NODES * EDGE_IN
                             + (size_t)gid[m0 + arow] * EDGE_IN + aq * 8;
    const uint32_t aSt = sb + arow * 80 + aq * 16;

    float4 av[2][2];   // two prefetch buffers, 2 float4 each
    auto ldA = [&](int b, int kt) {
        const float4* p = (const float4*)(agF + kt * 32);
        av[b][0] = p[0]; av[b][1] = p[1];
    };
    auto stsA = [&](int b, int s) {
        sts128(aSt + s * A_ST,
               f2h2(av[b][0].x, av[b][0].y), f2h2(av[b][0].z, av[b][0].w),
               f2h2(av[b][1].x, av[b][1].y), f2h2(av[b][1].z, av[b][1].w));
    };

    float acc[2][4][4];
    #pragma unroll
    for (int i = 0; i < 2; ++i)
        #pragma unroll
        for (int j = 0; j < 4; ++j)
            #pragma unroll
            for (int q = 0; q < 4; ++q) acc[i][j][q] = 0.f;

    // ---- prologue: slots 0,1 get tiles 0,1; registers prefetch tiles 2,3
    ldA(0, 0); stsA(0, 0); cpB(0, 0); cp_commit();
    ldA(1, 1); stsA(1, 1); cpB(1, 1); cp_commit();
    ldA(0, 2); ldA(1, 3);

    for (int i = 0; i < NI; ++i) {
        cp_wait<0>();        // B of tiles 2i,2i+1 landed
        __syncthreads();     // slots (2i+2)&3,(2i+3)&3 free (consumed at i-1)

        const int k2 = 2 * i + 2;
        if (k2 < KT) {
            stsA(0, k2 & 3); stsA(1, (k2 + 1) & 3);
            cpB(k2 & 3, k2);           cp_commit();
            cpB((k2 + 1) & 3, k2 + 1); cp_commit();
            if (k2 + 2 < KT) { ldA(0, k2 + 2); ldA(1, k2 + 3); }
        } else {
            cp_commit(); cp_commit();
        }

        #pragma unroll
        for (int h = 0; h < 2; ++h) {
            const int s = (2 * i + h) & 3;
            const uint32_t Ab = sb + s * A_ST;
            const uint32_t Bb = sb + OFF_B + s * B_ST;
            #pragma unroll
            for (int kk = 0; kk < 2; ++kk) {
                uint32_t af[2][4];
                #pragma unroll
                for (int mt = 0; mt < 2; ++mt)
                    ldsm_x4(af[mt], Ab + (wm * 32 + mt * 16 + (l & 15)) * 80
                                       + kk * 32 + (l >> 4) * 16);
                uint32_t bf[4][2];
                #pragma unroll
                for (int ntp = 0; ntp < 2; ++ntp) {
                    const int krow = kk * 16 + ((l >> 3) & 1) * 8 + (l & 7);
                    const int c    = wn * 4 + ntp * 2 + (l >> 4);
                    uint32_t r[4];
                    ldsm_x4_t(r, Bb + krow * 256 + ((c >> 3) * 128)
                                 + (((c & 7) ^ (krow & 7)) << 4));
                    bf[2 * ntp][0] = r[0];     bf[2 * ntp][1] = r[1];
                    bf[2 * ntp + 1][0] = r[2]; bf[2 * ntp + 1][1] = r[3];
                }
                #pragma unroll
                for (int mt = 0; mt < 2; ++mt)
                    #pragma unroll
                    for (int nt = 0; nt < 4; ++nt)
                        mma_f16(acc[mt][nt], af[mt], bf[nt]);
            }
        }
    }

    const float* bias = ball + e * DOUT;
    #pragma unroll
    for (int mt = 0; mt < 2; ++mt) {
        const int row = m0 + wm * 32 + mt * 16 + (l >> 2);
        #pragma unroll
        for (int nt = 0; nt < 4; ++nt) {
            const int col = wn * 32 + nt * 8 + (l & 3) * 2;
            const float2 bv = *(const float2*)&bias[col];
            float x0 = acc[mt][nt][0] + bv.x; x0 = x0 > 0.f ? x0 : 0.01f * x0;
            float x1 = acc[mt][nt][1] + bv.y; x1 = x1 > 0.f ? x1 : 0.01f * x1;
            float x2 = acc[mt][nt][2] + bv.x; x2 = x2 > 0.f ? x2 : 0.01f * x2;
            float x3 = acc[mt][nt][3] + bv.y; x3 = x3 > 0.f ? x3 : 0.01f * x3;
            *(__half2*)&g_agg[(size_t)row * HET_IN + e * DOUT + col]       = __floats2half2_rn(x0, x1);
            *(__half2*)&g_agg[(size_t)(row + 8) * HET_IN + e * DOUT + col] = __floats2half2_rn(x2, x3);
        }
    }
}

// ============================================================================
// GEMM2 (HET): 256 threads, BM=32, 8 warps (warp tile 16x32), 6-slot ring,
// two K-tiles per barrier, wait_group<2> -> 2 iterations of load slack.
// ============================================================================
__global__ void __launch_bounds__(256, 3) hetagg_het(
    const float* __restrict__ ball,
    float*       __restrict__ outFinal)
{
    constexpr int KT    = HET_IN / 32;      // 56
    constexpr int NI    = KT / 2;           // 28
    constexpr int A_ST  = 32 * 80;          // 2560
    constexpr int B_ST  = 32 * 256;         // 8192
    constexpr int OFF_B = 6 * A_ST;

    extern __shared__ char smem[];
    const uint32_t sb = (uint32_t)__cvta_generic_to_shared(smem);

    const int tid  = threadIdx.x;
    const int l    = tid & 31;
    const int warp = tid >> 5;
    const int wm   = warp >> 2;     // 0..1 (16-row band)
    const int wn   = warp & 3;      // 0..3
    const int m0   = blockIdx.x * 32;

    // ---- B loader: 2 cp16/thread/ktile
    const int bk = tid >> 3;
    const int bc = (tid & 7) * 2;
    const __half* bsrc = g_WH + (size_t)bk * DOUT + bc * 8;
    const uint32_t bdst0 = sb + OFF_B + bk * 256 + ((bc >> 3) * 128) + (((bc & 7) ^ (bk & 7)) * 16);
    const int bc1 = bc + 1;
    const uint32_t bdst1 = sb + OFF_B + bk * 256 + ((bc1 >> 3) * 128) + (((bc1 & 7) ^ (bk & 7)) * 16);

    // ---- A loader: threads 0..127, 1 cp16 each
    const int arow = tid >> 2, ac = tid & 3;
    const __half* agH  = g_agg + (size_t)(m0 + arow) * HET_IN + ac * 8;
    const uint32_t adst = sb + arow * 80 + ac * 16;

    auto fill = [&](int s, int kt) {
        if (tid < 128) cp16(adst + s * A_ST, agH + kt * 32);
        const __half* src = bsrc + (size_t)kt * 32 * DOUT;
        cp16(bdst0 + s * B_ST, src);
        cp16(bdst1 + s * B_ST, src + 8);
        cp_commit();
    };

    float acc[1][4][4];
    #pragma unroll
    for (int j = 0; j < 4; ++j)
        #pragma unroll
        for (int q = 0; q < 4; ++q) acc[0][j][q] = 0.f;

    // ---- prologue: tiles 0..3 into slots 0..3 (4 groups)
    fill(0, 0); fill(1, 1); fill(2, 2); fill(3, 3);

    for (int i = 0; i < NI; ++i) {
        cp_wait<2>();        // tiles 2i,2i+1 landed (2 newest groups may stay in flight)
        __syncthreads();

        const int k4 = 2 * i + 4;
        if (k4 < KT) { fill(k4 % 6, k4); fill((k4 + 1) % 6, k4 + 1); }
        else         { cp_commit(); cp_commit(); }

        #pragma unroll
        for (int h = 0; h < 2; ++h) {
            const int s = (2 * i + h) % 6;
            const uint32_t Ab = sb + s * A_ST;
            const uint32_t Bb = sb + OFF_B + s * B_ST;
            #pragma unroll
            for (int kk = 0; kk < 2; ++kk) {
                uint32_t af[1][4];
                ldsm_x4(af[0], Ab + (wm * 16 + (l & 15)) * 80
                                  + kk * 32 + (l >> 4) * 16);
                uint32_t bf[4][2];
                #pragma unroll
                for (int ntp = 0; ntp < 2; ++ntp) {
                    const int krow = kk * 16 + ((l >> 3) & 1) * 8 + (l & 7);
                    const int c    = wn * 4 + ntp * 2 + (l >> 4);
                    uint32_t r[4];
                    ldsm_x4_t(r, Bb + krow * 256 + ((c >> 3) * 128)
                                 + (((c & 7) ^ (krow & 7)) << 4));
                    bf[2 * ntp][0] = r[0];     bf[2 * ntp][1] = r[1];
                    bf[2 * ntp + 1][0] = r[2]; bf[2 * ntp + 1][1] = r[3];
                }
                #pragma unroll
                for (int nt = 0; nt < 4; ++nt)
                    mma_f16(acc[0][nt], af[0], bf[nt]);
            }
        }
    }

    #pragma unroll
    for (int nt = 0; nt < 4; ++nt) {
        const int row = m0 + wm * 16 + (l >> 2);
        const int col = wn * 32 + nt * 8 + (l & 3) * 2;
        const float2 bv = *(const float2*)&ball[col];
        float x0 = acc[0][nt][0] + bv.x; x0 = x0 > 0.f ? x0 : 0.01f * x0;
        float x1 = acc[0][nt][1] + bv.y; x1 = x1 > 0.f ? x1 : 0.01f * x1;
        float x2 = acc[0][nt][2] + bv.x; x2 = x2 > 0.f ? x2 : 0.01f * x2;
        float x3 = acc[0][nt][3] + bv.y; x3 = x3 > 0.f ? x3 : 0.01f * x3;
        *(float2*)&outFinal[(size_t)row * DOUT + col]       = make_float2(x0, x1);
        *(float2*)&outFinal[(size_t)(row + 8) * DOUT + col] = make_float2(x2, x3);
    }
}

extern "C" void kernel_launch(void* const* d_in, const int* in_sizes, int n_in,
                              void* d_out, int out_size) {
    const float* features = (const float*)d_in[0];
    const float* W_edge   = (const float*)d_in[1];
    const float* b_edge   = (const float*)d_in[2];
    const float* W_het    = (const float*)d_in[3];
    const float* b_het    = (const float*)d_in[4];
    const int*   gid      = (const int*)d_in[5];
    float* out = (float*)d_out;

    __half* we; cudaGetSymbolAddress((void**)&we, g_WE);
    __half* wh; cudaGetSymbolAddress((void**)&wh, g_WH);

    const int n4e = NUM_EDGE * EDGE_IN * DOUT / 4;
    const int n4h = HET_IN * DOUT / 4;
    cvt_to_half<<<(n4e + 255) / 256, 256>>>((const float4*)W_edge, (__half2*)we, n4e);
    cvt_to_half<<<(n4h + 255) / 256, 256>>>((const float4*)W_het, (__half2*)wh, n4h);

    const int smem1 = 4 * (128 * 80) + 4 * (32 * 256);  // 73728
    const int smem2 = 6 * (32 * 80)  + 6 * (32 * 256);  // 64512

    cudaFuncSetAttribute(hetagg_edge,
                         cudaFuncAttributeMaxDynamicSharedMemorySize, smem1);
    cudaFuncSetAttribute(hetagg_het,
                         cudaFuncAttributeMaxDynamicSharedMemorySize, smem2);

    dim3 g1(BATCH / 128, NUM_EDGE);
    hetagg_edge<<<g1, 512, smem1>>>(features, gid, b_edge);

    dim3 g2(BATCH / 32, 1);
    hetagg_het<<<g2, 256, smem2>>>(b_het, out);
}

// round 8
// speedup vs baseline: 1.2809x; 1.2809x over previous
#include <cuda_runtime.h>
#include <cuda_fp16.h>
#include <cstdint>

#define NUM_EDGE  14
#define NUM_NODES 10000
#define BATCH     8192
#define EDGE_IN   1536
#define HET_IN    1792
#define DOUT      128

__device__ __half g_agg[(size_t)BATCH * HET_IN];
__device__ __half g_WE [(size_t)NUM_EDGE * EDGE_IN * DOUT];
__device__ __half g_WH [(size_t)HET_IN * DOUT];
__device__ float  g_part[2][(size_t)BATCH * DOUT];

__device__ __forceinline__ uint32_t f2h2(float x, float y) {
    __half2 h = __floats2half2_rn(x, y);
    return *(uint32_t*)&h;
}

__device__ __forceinline__ void cp16(uint32_t s, const void* g) {
    asm volatile("cp.async.cg.shared.global [%0], [%1], 16;\n" :: "r"(s), "l"(g));
}
__device__ __forceinline__ void cp_commit() { asm volatile("cp.async.commit_group;\n"); }
template <int N> __device__ __forceinline__ void cp_wait() {
    asm volatile("cp.async.wait_group %0;\n" :: "n"(N));
}

__device__ __forceinline__ void ldsm_x4(uint32_t* r, uint32_t a) {
    asm volatile("ldmatrix.sync.aligned.m8n8.x4.shared.b16 {%0,%1,%2,%3}, [%4];"
        : "=r"(r[0]), "=r"(r[1]), "=r"(r[2]), "=r"(r[3]) : "r"(a));
}
__device__ __forceinline__ void ldsm_x4_t(uint32_t* r, uint32_t a) {
    asm volatile("ldmatrix.sync.aligned.m8n8.x4.trans.shared.b16 {%0,%1,%2,%3}, [%4];"
        : "=r"(r[0]), "=r"(r[1]), "=r"(r[2]), "=r"(r[3]) : "r"(a));
}
__device__ __forceinline__ void sts128(uint32_t a, uint32_t x, uint32_t y, uint32_t z, uint32_t w) {
    asm volatile("st.shared.v4.b32 [%0], {%1,%2,%3,%4};" :: "r"(a), "r"(x), "r"(y), "r"(z), "r"(w));
}

__device__ __forceinline__ void mma_f16(float* c, const uint32_t* a, const uint32_t* b) {
    asm volatile(
        "mma.sync.aligned.m16n8k16.row.col.f32.f16.f16.f32 "
        "{%0,%1,%2,%3}, {%4,%5,%6,%7}, {%8,%9}, {%0,%1,%2,%3};\n"
        : "+f"(c[0]), "+f"(c[1]), "+f"(c[2]), "+f"(c[3])
        : "r"(a[0]), "r"(a[1]), "r"(a[2]), "r"(a[3]), "r"(b[0]), "r"(b[1]));
}

__global__ void cvt_to_half(const float4* __restrict__ s, __half2* __restrict__ d, int n4) {
    int i = blockIdx.x * blockDim.x + threadIdx.x;
    if (i < n4) {
        float4 v = s[i];
        d[2 * i]     = __floats2half2_rn(v.x, v.y);
        d[2 * i + 1] = __floats2half2_rn(v.z, v.w);
    }
}

// ============================================================================
// GEMM1 (EDGE): 512 threads, BM=256, 16 warps (4x4 grid of 64x32 warp tiles),
// 4-slot ring, two K-tiles per barrier. A gathered fp32->fp16 at STS.
// B tile shared across 256 rows -> B DRAM/L2 traffic halved vs BM=128.
// ============================================================================
__global__ void __launch_bounds__(512, 1) hetagg_edge(
    const float* __restrict__ Afeat,
    const int*   __restrict__ gid,
    const float* __restrict__ ball)
{
    constexpr int KT    = EDGE_IN / 32;     // 48
    constexpr int NI    = KT / 2;           // 24
    constexpr int A_ST  = 256 * 80;         // 20480
    constexpr int B_ST  = 32 * 256;         // 8192
    constexpr int OFF_B = 4 * A_ST;

    extern __shared__ char smem[];
    const uint32_t sb = (uint32_t)__cvta_generic_to_shared(smem);

    const int e    = blockIdx.y;
    const int tid  = threadIdx.x;
    const int l    = tid & 31;
    const int warp = tid >> 5;
    const int wm   = warp >> 2;     // 0..3 (64-row band)
    const int wn   = warp & 3;      // 0..3 (32-col band)
    const int m0   = blockIdx.x * 256;

    // ---- B loader: 1 cp16/thread/ktile (512 threads for 8KB tile)
    const __half* Bh = g_WE + (size_t)e * EDGE_IN * DOUT;
    const int bk = tid >> 4;
    const int bc = tid & 15;
    const __half* bsrc = Bh + (size_t)bk * DOUT + bc * 8;
    const uint32_t bdst = sb + OFF_B + bk * 256 + ((bc >> 3) * 128) + (((bc & 7) ^ (bk & 7)) * 16);
    auto cpB = [&](int s, int kt) {
        cp16(bdst + s * B_ST, bsrc + (size_t)kt * 32 * DOUT);
    };

    // ---- A loader: 2 threads/row, 16 floats each per ktile (256 rows)
    const int arow = tid >> 1, ah = tid & 1;
    const float* agF = Afeat + (size_t)e * NUM_NODES * EDGE_IN
                             + (size_t)gid[m0 + arow] * EDGE_IN + ah * 16;
    const uint32_t aSt = sb + arow * 80 + ah * 32;

    float4 av[2][4];
    auto ldA = [&](int b, int kt) {
        const float4* p = (const float4*)(agF + kt * 32);
        av[b][0] = p[0]; av[b][1] = p[1]; av[b][2] = p[2]; av[b][3] = p[3];
    };
    auto stsA = [&](int b, int s) {
        sts128(aSt + s * A_ST,
               f2h2(av[b][0].x, av[b][0].y), f2h2(av[b][0].z, av[b][0].w),
               f2h2(av[b][1].x, av[b][1].y), f2h2(av[b][1].z, av[b][1].w));
        sts128(aSt + s * A_ST + 16,
               f2h2(av[b][2].x, av[b][2].y), f2h2(av[b][2].z, av[b][2].w),
               f2h2(av[b][3].x, av[b][3].y), f2h2(av[b][3].z, av[b][3].w));
    };

    float acc[2][4][4];
    #pragma unroll
    for (int i = 0; i < 2; ++i)
        #pragma unroll
        for (int j = 0; j < 4; ++j)
            #pragma unroll
            for (int q = 0; q < 4; ++q) acc[i][j][q] = 0.f;
    // acc covers warp tile 64x32 as 4 mt x 4 nt? No: 64x32 = 4 mt (16) x 4 nt (8).
    // Keep R4's [WMT=4] layout via two halves: acc2 below holds mt=2,3.
    float acc2[2][4][4];
    #pragma unroll
    for (int i = 0; i < 2; ++i)
        #pragma unroll
        for (int j = 0; j < 4; ++j)
            #pragma unroll
            for (int q = 0; q < 4; ++q) acc2[i][j][q] = 0.f;

    // ---- prologue: slots 0,1 get tiles 0,1; registers prefetch tiles 2,3
    ldA(0, 0); stsA(0, 0); cpB(0, 0); cp_commit();
    ldA(1, 1); stsA(1, 1); cpB(1, 1); cp_commit();
    ldA(0, 2); ldA(1, 3);

    for (int i = 0; i < NI; ++i) {
        cp_wait<0>();        // B of tiles 2i,2i+1 landed
        __syncthreads();     // slots (2i+2)&3,(2i+3)&3 free (consumed at i-1)

        const int k2 = 2 * i + 2;
        if (k2 < KT) {
            stsA(0, k2 & 3); stsA(1, (k2 + 1) & 3);
            cpB(k2 & 3, k2);           cp_commit();
            cpB((k2 + 1) & 3, k2 + 1); cp_commit();
            if (k2 + 2 < KT) { ldA(0, k2 + 2); ldA(1, k2 + 3); }
        } else {
            cp_commit(); cp_commit();
        }

        #pragma unroll
        for (int h = 0; h < 2; ++h) {
            const int s = (2 * i + h) & 3;
            const uint32_t Ab = sb + s * A_ST;
            const uint32_t Bb = sb + OFF_B + s * B_ST;
            #pragma unroll
            for (int kk = 0; kk < 2; ++kk) {
                uint32_t af[4][4];
                #pragma unroll
                for (int mt = 0; mt < 4; ++mt)
                    ldsm_x4(af[mt], Ab + (wm * 64 + mt * 16 + (l & 15)) * 80
                                       + kk * 32 + (l >> 4) * 16);
                uint32_t bf[4][2];
                #pragma unroll
                for (int ntp = 0; ntp < 2; ++ntp) {
                    const int krow = kk * 16 + ((l >> 3) & 1) * 8 + (l & 7);
                    const int c    = wn * 4 + ntp * 2 + (l >> 4);
                    uint32_t r[4];
                    ldsm_x4_t(r, Bb + krow * 256 + ((c >> 3) * 128)
                                 + (((c & 7) ^ (krow & 7)) << 4));
                    bf[2 * ntp][0] = r[0];     bf[2 * ntp][1] = r[1];
                    bf[2 * ntp + 1][0] = r[2]; bf[2 * ntp + 1][1] = r[3];
                }
                #pragma unroll
                for (int mt = 0; mt < 2; ++mt)
                    #pragma unroll
                    for (int nt = 0; nt < 4; ++nt)
                        mma_f16(acc[mt][nt], af[mt], bf[nt]);
                #pragma unroll
                for (int mt = 0; mt < 2; ++mt)
                    #pragma unroll
                    for (int nt = 0; nt < 4; ++nt)
                        mma_f16(acc2[mt][nt], af[2 + mt], bf[nt]);
            }
        }
    }

    const float* bias = ball + e * DOUT;
    #pragma unroll
    for (int half = 0; half < 2; ++half) {
        float (*ac)[4][4] = half ? acc2 : acc;
        #pragma unroll
        for (int mt = 0; mt < 2; ++mt) {
            const int row = m0 + wm * 64 + (half * 2 + mt) * 16 + (l >> 2);
            #pragma unroll
            for (int nt = 0; nt < 4; ++nt) {
                const int col = wn * 32 + nt * 8 + (l & 3) * 2;
                const float2 bv = *(const float2*)&bias[col];
                float x0 = ac[mt][nt][0] + bv.x; x0 = x0 > 0.f ? x0 : 0.01f * x0;
                float x1 = ac[mt][nt][1] + bv.y; x1 = x1 > 0.f ? x1 : 0.01f * x1;
                float x2 = ac[mt][nt][2] + bv.x; x2 = x2 > 0.f ? x2 : 0.01f * x2;
                float x3 = ac[mt][nt][3] + bv.y; x3 = x3 > 0.f ? x3 : 0.01f * x3;
                *(__half2*)&g_agg[(size_t)row * HET_IN + e * DOUT + col]       = __floats2half2_rn(x0, x1);
                *(__half2*)&g_agg[(size_t)(row + 8) * HET_IN + e * DOUT + col] = __floats2half2_rn(x2, x3);
            }
        }
    }
}

// ============================================================================
// GEMM2 (HET): split-K=2. 256 threads, BM=64, 8 warps (2x4 of 32x32),
// 3-slot ring, one K-tile per barrier. Partials (no bias) -> g_part[split].
// ============================================================================
__global__ void __launch_bounds__(256, 3) hetagg_het(void)
{
    constexpr int KT_H  = (HET_IN / 2) / 32;   // 28 ktiles per split
    constexpr int A_ST  = 64 * 80;             // 5120
    constexpr int B_ST  = 32 * 256;            // 8192
    constexpr int OFF_B = 3 * A_ST;

    extern __shared__ char smem[];
    const uint32_t sb = (uint32_t)__cvta_generic_to_shared(smem);

    const int tid  = threadIdx.x;
    const int l    = tid & 31;
    const int warp = tid >> 5;
    const int wm   = warp >> 2;     // 0..1
    const int wn   = warp & 3;      // 0..3
    const int m0   = blockIdx.x * 64;
    const int kOff = blockIdx.y * (HET_IN / 2);   // split offset in K

    // ---- B loader: 2 cp16/thread/ktile
    const int bk = tid >> 3;
    const int bc = (tid & 7) * 2;
    const __half* bsrc = g_WH + (size_t)(kOff + bk) * DOUT + bc * 8;
    const uint32_t bdst0 = sb + OFF_B + bk * 256 + ((bc >> 3) * 128) + (((bc & 7) ^ (bk & 7)) * 16);
    const int bc1 = bc + 1;
    const uint32_t bdst1 = sb + OFF_B + bk * 256 + ((bc1 >> 3) * 128) + (((bc1 & 7) ^ (bk & 7)) * 16);

    // ---- A loader: 4 threads/row, 1 cp16 each (64 rows x 32 halfs)
    const int arow = tid >> 2, ac = tid & 3;
    const __half* agH  = g_agg + (size_t)(m0 + arow) * HET_IN + kOff + ac * 8;
    const uint32_t adst = sb + arow * 80 + ac * 16;

    auto fill = [&](int s, int kt) {
        cp16(adst + s * A_ST, agH + kt * 32);
        const __half* src = bsrc + (size_t)kt * 32 * DOUT;
        cp16(bdst0 + s * B_ST, src);
        cp16(bdst1 + s * B_ST, src + 8);
        cp_commit();
    };

    float acc[2][4][4];
    #pragma unroll
    for (int i = 0; i < 2; ++i)
        #pragma unroll
        for (int j = 0; j < 4; ++j)
            #pragma unroll
            for (int q = 0; q < 4; ++q) acc[i][j][q] = 0.f;

    fill(0, 0); fill(1, 1);

    for (int kt = 0; kt < KT_H; ++kt) {
        cp_wait<1>();
        __syncthreads();

        if (kt + 2 < KT_H) fill((kt + 2) % 3, kt + 2);
        else               cp_commit();

        const int s = kt % 3;
        const uint32_t Ab = sb + s * A_ST;
        const uint32_t Bb = sb + OFF_B + s * B_ST;
        #pragma unroll
        for (int kk = 0; kk < 2; ++kk) {
            uint32_t af[2][4];
            #pragma unroll
            for (int mt = 0; mt < 2; ++mt)
                ldsm_x4(af[mt], Ab + (wm * 32 + mt * 16 + (l & 15)) * 80
                                   + kk * 32 + (l >> 4) * 16);
            uint32_t bf[4][2];
            #pragma unroll
            for (int ntp = 0; ntp < 2; ++ntp) {
                const int krow = kk * 16 + ((l >> 3) & 1) * 8 + (l & 7);
                const int c    = wn * 4 + ntp * 2 + (l >> 4);
                uint32_t r[4];
                ldsm_x4_t(r, Bb + krow * 256 + ((c >> 3) * 128)
                             + (((c & 7) ^ (krow & 7)) << 4));
                bf[2 * ntp][0] = r[0];     bf[2 * ntp][1] = r[1];
                bf[2 * ntp + 1][0] = r[2]; bf[2 * ntp + 1][1] = r[3];
            }
            #pragma unroll
            for (int mt = 0; mt < 2; ++mt)
                #pragma unroll
                for (int nt = 0; nt < 4; ++nt)
                    mma_f16(acc[mt][nt], af[mt], bf[nt]);
        }
    }

    float* part = g_part[blockIdx.y];
    #pragma unroll
    for (int mt = 0; mt < 2; ++mt) {
        const int row = m0 + wm * 32 + mt * 16 + (l >> 2);
        #pragma unroll
        for (int nt = 0; nt < 4; ++nt) {
            const int col = wn * 32 + nt * 8 + (l & 3) * 2;
            *(float2*)&part[(size_t)row * DOUT + col] =
                make_float2(acc[mt][nt][0], acc[mt][nt][1]);
            *(float2*)&part[(size_t)(row + 8) * DOUT + col] =
                make_float2(acc[mt][nt][2], acc[mt][nt][3]);
        }
    }
}

// reduce: out = leaky(p0 + p1 + bias)
__global__ void het_reduce(const float* __restrict__ ball, float* __restrict__ out) {
    const int i = blockIdx.x * blockDim.x + threadIdx.x;   // float4 index
    const int n4 = BATCH * DOUT / 4;
    if (i >= n4) return;
    float4 a = ((const float4*)g_part[0])[i];
    float4 b = ((const float4*)g_part[1])[i];
    const int col = (i * 4) & (DOUT - 1);
    float4 bv = *(const float4*)&ball[col];
    float x0 = a.x + b.x + bv.x; x0 = x0 > 0.f ? x0 : 0.01f * x0;
    float x1 = a.y + b.y + bv.y; x1 = x1 > 0.f ? x1 : 0.01f * x1;
    float x2 = a.z + b.z + bv.z; x2 = x2 > 0.f ? x2 : 0.01f * x2;
    float x3 = a.w + b.w + bv.w; x3 = x3 > 0.f ? x3 : 0.01f * x3;
    ((float4*)out)[i] = make_float4(x0, x1, x2, x3);
}

extern "C" void kernel_launch(void* const* d_in, const int* in_sizes, int n_in,
                              void* d_out, int out_size) {
    const float* features = (const float*)d_in[0];
    const float* W_edge   = (const float*)d_in[1];
    const float* b_edge   = (const float*)d_in[2];
    const float* W_het    = (const float*)d_in[3];
    const float* b_het    = (const float*)d_in[4];
    const int*   gid      = (const int*)d_in[5];
    float* out = (float*)d_out;

    __half* we; cudaGetSymbolAddress((void**)&we, g_WE);
    __half* wh; cudaGetSymbolAddress((void**)&wh, g_WH);

    const int n4e = NUM_EDGE * EDGE_IN * DOUT / 4;
    const int n4h = HET_IN * DOUT / 4;
    cvt_to_half<<<(n4e + 255) / 256, 256>>>((const float4*)W_edge, (__half2*)we, n4e);
    cvt_to_half<<<(n4h + 255) / 256, 256>>>((const float4*)W_het, (__half2*)wh, n4h);

    const int smem1 = 4 * (256 * 80) + 4 * (32 * 256);  // 114688
    const int smem2 = 3 * (64 * 80)  + 3 * (32 * 256);  // 39936

    cudaFuncSetAttribute(hetagg_edge,
                         cudaFuncAttributeMaxDynamicSharedMemorySize, smem1);
    cudaFuncSetAttribute(hetagg_het,
                         cudaFuncAttributeMaxDynamicSharedMemorySize, smem2);

    dim3 g1(BATCH / 256, NUM_EDGE);
    hetagg_edge<<<g1, 512, smem1>>>(features, gid, b_edge);

    dim3 g2(BATCH / 64, 2);
    hetagg_het<<<g2, 256, smem2>>>();

    const int n4o = BATCH * DOUT / 4;
    het_reduce<<<(n4o + 255) / 256, 256>>>(b_het, out);
}